// round 2
// baseline (speedup 1.0000x reference)
#include <cuda_runtime.h>
#include <cuda_bf16.h>
#include <math.h>

// Problem constants
#define C 144
#define W 77
#define KW 10
#define FC 64
#define CONV_OUT 68           // W - KW + 1
#define CONCAT_N (C*FC + CONV_OUT)   // 9284
#define H2 128

// Scratch (no allocations allowed)
__device__ __align__(16) float g_concat[CONCAT_N];
__device__ float g_h[H2];
__device__ int g_flag;

__device__ __forceinline__ float warp_reduce(float v) {
    #pragma unroll
    for (int o = 16; o > 0; o >>= 1) v += __shfl_xor_sync(0xffffffffu, v, o);
    return v;
}

// K1: per-channel FC GEMVs (blocks 0..143) + conv (block 144). Also resets g_flag.
__global__ __launch_bounds__(256) void k1_fc_conv(
    const float* __restrict__ x,       // [C, W]
    const float* __restrict__ fc_w,    // [C, FC, W]
    const float* __restrict__ fc_b,    // [C, FC]
    const float* __restrict__ conv_w,  // [C, KW]
    const float* __restrict__ conv_b)  // [1]
{
    const int b = blockIdx.x;
    const int tid = threadIdx.x;
    const int warp = tid >> 5, lane = tid & 31;

    if (b == 0 && tid == 0) g_flag = 0;

    if (b < C) {
        __shared__ float xs[W];
        if (tid < W) xs[tid] = x[b * W + tid];
        __syncthreads();

        // 8 warps x 8 outputs each = 64 outputs (FC)
        #pragma unroll
        for (int i = 0; i < 8; i++) {
            const int d = warp * 8 + i;
            const float* wrow = fc_w + (size_t)(b * FC + d) * W;
            float s = wrow[lane] * xs[lane];
            if (lane < 45) s += wrow[lane + 32] * xs[lane + 32];
            if (lane < 13) s += wrow[lane + 64] * xs[lane + 64];
            s = warp_reduce(s);
            if (lane == 0) g_concat[b * FC + d] = s + fc_b[b * FC + d];
        }
    } else {
        // Conv block: conv[o] = sum_{c,k} conv_w[c,k] * x[c, o+k]
        __shared__ float cw[C * KW];
        for (int i = tid; i < C * KW; i += 256) cw[i] = conv_w[i];
        __syncthreads();
        const float cb = conv_b[0];
        for (int o = warp; o < CONV_OUT; o += 8) {
            float s = 0.f;
            for (int i = lane; i < C * KW; i += 32) {
                const int c = i / KW, k = i - c * KW;
                s += cw[i] * __ldg(&x[c * W + o + k]);
            }
            s = warp_reduce(s);
            if (lane == 0) g_concat[C * FC + o] = s + cb;
        }
    }
}

// K2: h[j] = relu(w2[j,:] . concat + b2[j]); last block does the scalar head.
__global__ __launch_bounds__(256) void k2_head(
    const float* __restrict__ w2,   // [H2, CONCAT_N]
    const float* __restrict__ b2,   // [H2]
    const float* __restrict__ w3,   // [1, H2]
    const float* __restrict__ b3,   // [1]
    float* __restrict__ out)        // [1]
{
    const int j = blockIdx.x;       // row 0..127
    const int tid = threadIdx.x;
    const int warp = tid >> 5, lane = tid & 31;

    const float4* __restrict__ wrow = reinterpret_cast<const float4*>(w2 + (size_t)j * CONCAT_N);
    const float4* __restrict__ cc   = reinterpret_cast<const float4*>(g_concat);

    float s = 0.f;
    // CONCAT_N/4 = 2321 float4 elements
    #pragma unroll 4
    for (int i = tid; i < CONCAT_N / 4; i += 256) {
        const float4 a = wrow[i];
        const float4 c = cc[i];
        s += a.x * c.x + a.y * c.y + a.z * c.z + a.w * c.w;
    }
    s = warp_reduce(s);

    __shared__ float red[8];
    if (lane == 0) red[warp] = s;
    __syncthreads();
    if (warp == 0) {
        s = (lane < 8) ? red[lane] : 0.f;
        s = warp_reduce(s);
        if (lane == 0) {
            const float h = fmaxf(s + b2[j], 0.f);
            g_h[j] = h;
            __threadfence();
            const int n = atomicAdd(&g_flag, 1);
            if (n == H2 - 1) {
                __threadfence();
                float acc = b3[0];
                #pragma unroll 8
                for (int q = 0; q < H2; q++) acc += w3[q] * g_h[q];
                acc = fmaxf(acc, 0.f);
                out[0] = 1.f / (1.f + expf(-acc));
            }
        }
    }
}

extern "C" void kernel_launch(void* const* d_in, const int* in_sizes, int n_in,
                              void* d_out, int out_size) {
    const float* x      = (const float*)d_in[0];
    const float* fc_w   = (const float*)d_in[1];
    const float* fc_b   = (const float*)d_in[2];
    const float* conv_w = (const float*)d_in[3];
    const float* conv_b = (const float*)d_in[4];
    const float* w2     = (const float*)d_in[5];
    const float* b2     = (const float*)d_in[6];
    const float* w3     = (const float*)d_in[7];
    const float* b3     = (const float*)d_in[8];
    float* out = (float*)d_out;

    k1_fc_conv<<<C + 1, 256>>>(x, fc_w, fc_b, conv_w, conv_b);
    k2_head<<<H2, 256>>>(w2, b2, w3, b3, out);
}

// round 4
// speedup vs baseline: 3.0203x; 3.0203x over previous
#include <cuda_runtime.h>
#include <cuda_bf16.h>
#include <math.h>

// Problem constants
#define C 144
#define W 77
#define KW 10
#define FC 64
#define CONV_OUT 68                  // W - KW + 1
#define FC_N (C*FC)                  // 9216
#define CONCAT_N (FC_N + CONV_OUT)   // 9284
#define CONCAT_V4 (CONCAT_N/4)       // 2321
#define H2 128
#define SPLIT 4
#define CHUNK 581                    // ceil(2321/4)

#define FC_BLOCKS (FC_N/64/8*8/8)    // 1152 = 9216 warps / 8 warps per block
#define K1_GRID (1152 + CONV_OUT)    // 1220

// Scratch (no allocations allowed)
__device__ __align__(16) float g_concat[CONCAT_N];
__device__ float g_acc[H2];
__device__ int g_flag;

__device__ __forceinline__ float warp_reduce(float v) {
    #pragma unroll
    for (int o = 16; o > 0; o >>= 1) v += __shfl_xor_sync(0xffffffffu, v, o);
    return v;
}

// K1: one warp per FC output (blocks 0..1151), one block per conv output (1152..1219).
// Block 0 also resets the k2 scratch (stream-ordered before k2).
__global__ __launch_bounds__(256) void k1_fc_conv(
    const float* __restrict__ x,       // [C, W]
    const float* __restrict__ fc_w,    // [C, FC, W] == [9216, 77]
    const float* __restrict__ fc_b,    // [C, FC]
    const float* __restrict__ conv_w,  // [C, KW] = 1440
    const float* __restrict__ conv_b)  // [1]
{
    const int b = blockIdx.x;
    const int tid = threadIdx.x;
    const int warp = tid >> 5, lane = tid & 31;

    if (b == 0) {
        if (tid < H2) g_acc[tid] = 0.f;
        if (tid == 0) g_flag = 0;
    }

    if (b < 1152) {
        const int w = b * 8 + warp;            // global output index 0..9215
        const int c = w >> 6;                  // channel
        const float* __restrict__ wrow = fc_w + (size_t)w * W;
        const float* __restrict__ xr   = x + c * W;
        float s = wrow[lane] * xr[lane] + wrow[lane + 32] * xr[lane + 32];
        if (lane < 13) s += wrow[lane + 64] * xr[lane + 64];
        s = warp_reduce(s);
        if (lane == 0) g_concat[w] = s + fc_b[w];
    } else {
        const int o = b - 1152;                // conv output 0..67
        float s = 0.f;
        #pragma unroll
        for (int i = tid; i < C * KW; i += 256) {
            const int c = i / KW, k = i - c * KW;
            s += conv_w[i] * x[c * W + o + k];
        }
        s = warp_reduce(s);
        __shared__ float red[8];
        if (lane == 0) red[warp] = s;
        __syncthreads();
        if (tid == 0) {
            float t = red[0];
            #pragma unroll
            for (int q = 1; q < 8; q++) t += red[q];
            g_concat[FC_N + o] = t + conv_b[0];
        }
    }
}

// K2: split-K GEMV. 512 blocks = 128 rows x 4 K-chunks. Last block runs the head.
__global__ __launch_bounds__(256) void k2_head(
    const float* __restrict__ w2,   // [H2, CONCAT_N]
    const float* __restrict__ b2,   // [H2]
    const float* __restrict__ w3,   // [1, H2]
    const float* __restrict__ b3,   // [1]
    float* __restrict__ out)        // [1]
{
    const int blk = blockIdx.x;
    const int j  = blk >> 2;        // row 0..127
    const int sp = blk & 3;         // chunk 0..3
    const int tid = threadIdx.x;
    const int warp = tid >> 5, lane = tid & 31;

    const int start = sp * CHUNK;
    const int end = (start + CHUNK < CONCAT_V4) ? start + CHUNK : CONCAT_V4;

    const float4* __restrict__ wrow = reinterpret_cast<const float4*>(w2 + (size_t)j * CONCAT_N);
    const float4* __restrict__ cc   = reinterpret_cast<const float4*>(g_concat);

    float s = 0.f;
    for (int i = start + tid; i < end; i += 256) {
        const float4 a = wrow[i];
        const float4 c = cc[i];
        s += a.x * c.x + a.y * c.y + a.z * c.z + a.w * c.w;
    }
    s = warp_reduce(s);

    __shared__ float red[8];
    __shared__ int is_last;
    if (lane == 0) red[warp] = s;
    if (tid == 0) is_last = 0;
    __syncthreads();

    if (tid == 0) {
        float t = red[0];
        #pragma unroll
        for (int q = 1; q < 8; q++) t += red[q];
        atomicAdd(&g_acc[j], t);
        __threadfence();
        const int n = atomicAdd(&g_flag, 1);
        if (n == H2 * SPLIT - 1) is_last = 1;
    }
    __syncthreads();

    if (is_last && warp == 0) {
        __threadfence();
        // head: lane q handles rows q, q+32, q+64, q+96
        float acc = 0.f;
        #pragma unroll
        for (int q = 0; q < 4; q++) {
            const int r = lane + q * 32;
            const float h = fmaxf(g_acc[r] + b2[r], 0.f);
            acc += w3[r] * h;
        }
        acc = warp_reduce(acc);
        if (lane == 0) {
            acc = fmaxf(acc + b3[0], 0.f);
            out[0] = 1.f / (1.f + expf(-acc));
        }
    }
}

extern "C" void kernel_launch(void* const* d_in, const int* in_sizes, int n_in,
                              void* d_out, int out_size) {
    const float* x      = (const float*)d_in[0];
    const float* fc_w   = (const float*)d_in[1];
    const float* fc_b   = (const float*)d_in[2];
    const float* conv_w = (const float*)d_in[3];
    const float* conv_b = (const float*)d_in[4];
    const float* w2     = (const float*)d_in[5];
    const float* b2     = (const float*)d_in[6];
    const float* w3     = (const float*)d_in[7];
    const float* b3     = (const float*)d_in[8];
    float* out = (float*)d_out;

    k1_fc_conv<<<K1_GRID, 256>>>(x, fc_w, fc_b, conv_w, conv_b);
    k2_head<<<H2 * SPLIT, 256>>>(w2, b2, w3, b3, out);
}

// round 5
// speedup vs baseline: 3.1015x; 1.0269x over previous
#include <cuda_runtime.h>
#include <cuda_bf16.h>
#include <math.h>

// Problem constants
#define C 144
#define W 77
#define KW 10
#define FC 64
#define CONV_OUT 68                  // W - KW + 1
#define FC_N (C*FC)                  // 9216
#define CONCAT_N (FC_N + CONV_OUT)   // 9284
#define CONCAT_V4 (CONCAT_N/4)       // 2321
#define H2 128
#define SPLIT 8
#define CHUNK 291                    // ceil(2321/8)

#define K1_GRID (1152 + CONV_OUT)    // 1220

// Scratch (no allocations allowed)
__device__ __align__(16) float g_concat[CONCAT_N];
__device__ float g_acc[H2];
__device__ int g_flag;

__device__ __forceinline__ float warp_reduce(float v) {
    #pragma unroll
    for (int o = 16; o > 0; o >>= 1) v += __shfl_xor_sync(0xffffffffu, v, o);
    return v;
}

// K1: one warp per FC output (blocks 0..1151), one block per conv output (1152..1219).
// Block 0 also resets the k2 scratch (stream-ordered before k2).
__global__ __launch_bounds__(256) void k1_fc_conv(
    const float* __restrict__ x,       // [C, W]
    const float* __restrict__ fc_w,    // [C, FC, W] == [9216, 77]
    const float* __restrict__ fc_b,    // [C, FC]
    const float* __restrict__ conv_w,  // [C, KW] = 1440
    const float* __restrict__ conv_b)  // [1]
{
    const int b = blockIdx.x;
    const int tid = threadIdx.x;
    const int warp = tid >> 5, lane = tid & 31;

    if (b == 0) {
        if (tid < H2) g_acc[tid] = 0.f;
        if (tid == 0) g_flag = 0;
    }

    if (b < 1152) {
        const int w = b * 8 + warp;            // global output index 0..9215
        const int c = w >> 6;                  // channel
        const float* __restrict__ wrow = fc_w + (size_t)w * W;
        const float* __restrict__ xr   = x + c * W;
        float s = wrow[lane] * xr[lane] + wrow[lane + 32] * xr[lane + 32];
        if (lane < 13) s += wrow[lane + 64] * xr[lane + 64];
        s = warp_reduce(s);
        if (lane == 0) g_concat[w] = s + fc_b[w];
    } else {
        const int o = b - 1152;                // conv output 0..67
        float s = 0.f;
        #pragma unroll
        for (int i = tid; i < C * KW; i += 256) {
            const int c = i / KW, k = i - c * KW;
            s += conv_w[i] * x[c * W + o + k];
        }
        s = warp_reduce(s);
        __shared__ float red[8];
        if (lane == 0) red[warp] = s;
        __syncthreads();
        if (tid == 0) {
            float t = red[0];
            #pragma unroll
            for (int q = 1; q < 8; q++) t += red[q];
            g_concat[FC_N + o] = t + conv_b[0];
        }
    }
}

// K2: split-K GEMV. 1024 blocks = 128 rows x 8 K-chunks. Last block runs the head.
__global__ __launch_bounds__(256, 8) void k2_head(
    const float* __restrict__ w2,   // [H2, CONCAT_N]
    const float* __restrict__ b2,   // [H2]
    const float* __restrict__ w3,   // [1, H2]
    const float* __restrict__ b3,   // [1]
    float* __restrict__ out)        // [1]
{
    const int blk = blockIdx.x;
    const int j  = blk >> 3;        // row 0..127
    const int sp = blk & 7;         // chunk 0..7
    const int tid = threadIdx.x;
    const int warp = tid >> 5, lane = tid & 31;

    const int start = sp * CHUNK;
    const int end = (start + CHUNK < CONCAT_V4) ? start + CHUNK : CONCAT_V4;

    const float4* __restrict__ wrow = reinterpret_cast<const float4*>(w2 + (size_t)j * CONCAT_N);
    const float4* __restrict__ cc   = reinterpret_cast<const float4*>(g_concat);

    float s = 0.f;
    for (int i = start + tid; i < end; i += 256) {
        const float4 a = wrow[i];
        const float4 c = cc[i];
        s += a.x * c.x + a.y * c.y + a.z * c.z + a.w * c.w;
    }
    s = warp_reduce(s);

    __shared__ float red[8];
    __shared__ int is_last;
    if (lane == 0) red[warp] = s;
    if (tid == 0) is_last = 0;
    __syncthreads();

    if (tid == 0) {
        float t = red[0];
        #pragma unroll
        for (int q = 1; q < 8; q++) t += red[q];
        atomicAdd(&g_acc[j], t);
        __threadfence();
        const int n = atomicAdd(&g_flag, 1);
        if (n == H2 * SPLIT - 1) is_last = 1;
    }
    __syncthreads();

    if (is_last && warp == 0) {
        __threadfence();
        // head: lane q handles rows q, q+32, q+64, q+96
        float acc = 0.f;
        #pragma unroll
        for (int q = 0; q < 4; q++) {
            const int r = lane + q * 32;
            const float h = fmaxf(g_acc[r] + b2[r], 0.f);
            acc += w3[r] * h;
        }
        acc = warp_reduce(acc);
        if (lane == 0) {
            acc = fmaxf(acc + b3[0], 0.f);
            out[0] = 1.f / (1.f + expf(-acc));
        }
    }
}

extern "C" void kernel_launch(void* const* d_in, const int* in_sizes, int n_in,
                              void* d_out, int out_size) {
    const float* x      = (const float*)d_in[0];
    const float* fc_w   = (const float*)d_in[1];
    const float* fc_b   = (const float*)d_in[2];
    const float* conv_w = (const float*)d_in[3];
    const float* conv_b = (const float*)d_in[4];
    const float* w2     = (const float*)d_in[5];
    const float* b2     = (const float*)d_in[6];
    const float* w3     = (const float*)d_in[7];
    const float* b3     = (const float*)d_in[8];
    float* out = (float*)d_out;

    k1_fc_conv<<<K1_GRID, 256>>>(x, fc_w, fc_b, conv_w, conv_b);
    k2_head<<<H2 * SPLIT, 256>>>(w2, b2, w3, b3, out);
}